// round 5
// baseline (speedup 1.0000x reference)
#include <cuda_runtime.h>
#include <stdint.h>

#define N_STRUCT   1000
#define ATOMS      100
#define N_SAMP     100000
#define N_GRAD     500000
#define DFEAT      128
#define NSEG       (N_STRUCT * ATOMS)      // 100000
#define ROW_F4     96                      // 3*128/4
#define GRAD_OUT_OFFSET (N_STRUCT * DFEAT)

#define CHAIN_BLOCKS  ((N_GRAD + 255) / 256)   // 1954
#define VALUES_BLOCKS (N_STRUCT / 2)           // 500 (2 structures / 256-thr block)
#define GATHER_BLOCKS (NSEG / 8)               // 12500 (8 warps/block, 1 seg/warp)

// -------- scratch (device globals; zero-initialized at module load) --------
// g_head invariant: all-zero (== empty, rows stored as i+1) at entry to
// kernel_launch; the gather kernel restores it every call.
__device__ int g_head[NSEG];
__device__ int g_next[N_GRAD];

// ---------------------------------------------------------------------------
// Kernel 1 (fused):
//   blocks [0, CHAIN_BLOCKS): build per-segment linked lists with atomicExch.
//   blocks [CHAIN_BLOCKS, +VALUES_BLOCKS): per-structure value sums
//     (structure_ids sorted -> binary search). Overlaps the atomic-latency-
//     bound chain build with bandwidth work.
// ---------------------------------------------------------------------------
__global__ void chain_values_kernel(const int*   __restrict__ gstruct,
                                    const int*   __restrict__ gatom,
                                    const float* __restrict__ values,
                                    const int*   __restrict__ sid,
                                    float*       __restrict__ out) {
    if (blockIdx.x < CHAIN_BLOCKS) {
        int i = blockIdx.x * 256 + threadIdx.x;
        if (i < N_GRAD) {
            int seg = gstruct[i] * ATOMS + gatom[i];
            int old = atomicExch(&g_head[seg], i + 1);   // i+1: 0 == empty
            g_next[i] = old;
        }
    } else {
        int vb   = blockIdx.x - CHAIN_BLOCKS;
        int half = threadIdx.x >> 7;            // 0 or 1
        int d    = threadIdx.x & 127;
        int s    = vb * 2 + half;

        __shared__ int s_lo[2], s_hi[2];
        if (d == 0) {
            int lo = 0, hi = N_SAMP;
            while (lo < hi) { int m = (lo + hi) >> 1; if (sid[m] < s) lo = m + 1; else hi = m; }
            s_lo[half] = lo;
            lo = s_lo[half]; hi = N_SAMP;
            while (lo < hi) { int m = (lo + hi) >> 1; if (sid[m] < s + 1) lo = m + 1; else hi = m; }
            s_hi[half] = lo;
        }
        __syncthreads();

        float acc = 0.f;
        int lo = s_lo[half], hi = s_hi[half];
        for (int r = lo; r < hi; ++r)
            acc += values[(long long)r * DFEAT + d];
        __stcs(out + (long long)s * DFEAT + d, acc);
    }
}

// ---------------------------------------------------------------------------
// Kernel 2: gather-reduce, one warp per segment, walking the linked list.
// Each chain step: issue next-pointer load + 3x512B data loads concurrently;
// serial chase latency is hidden by ~50 resident warps/SM (BW-bound).
// Resets g_head to 0 (restores invariant). Empty segments write zeros.
// ---------------------------------------------------------------------------
__global__ void gather_kernel(const float4* __restrict__ grad4,
                              float*        __restrict__ out_grad) {
    int warp_id = (blockIdx.x * 256 + threadIdx.x) >> 5;
    int lane    = threadIdx.x & 31;

    int h = g_head[warp_id];
    if (lane == 0) g_head[warp_id] = 0;     // restore invariant

    float4 a0 = make_float4(0.f, 0.f, 0.f, 0.f);
    float4 a1 = a0, a2 = a0;

    while (h > 0) {
        long long row = h - 1;
        int hn = g_next[row];               // uniform addr -> broadcast
        const float4* src = grad4 + row * ROW_F4;
        float4 v0 = __ldcs(src + lane);
        float4 v1 = __ldcs(src + lane + 32);
        float4 v2 = __ldcs(src + lane + 64);
        a0.x += v0.x; a0.y += v0.y; a0.z += v0.z; a0.w += v0.w;
        a1.x += v1.x; a1.y += v1.y; a1.z += v1.z; a1.w += v1.w;
        a2.x += v2.x; a2.y += v2.y; a2.z += v2.z; a2.w += v2.w;
        h = hn;
    }

    float4* dst = (float4*)(out_grad + (long long)warp_id * (3 * DFEAT));
    __stcs(dst + lane,      a0);
    __stcs(dst + lane + 32, a1);
    __stcs(dst + lane + 64, a2);
}

// ---------------------------------------------------------------------------
extern "C" void kernel_launch(void* const* d_in, const int* in_sizes, int n_in,
                              void* d_out, int out_size) {
    const float*  values  = (const float*)d_in[0];
    const int*    sid     = (const int*)  d_in[1];
    const float4* grad4   = (const float4*)d_in[2];
    const int*    gstruct = (const int*)  d_in[3];
    const int*    gatom   = (const int*)  d_in[4];

    float* out      = (float*)d_out;
    float* out_grad = out + GRAD_OUT_OFFSET;

    chain_values_kernel<<<CHAIN_BLOCKS + VALUES_BLOCKS, 256>>>(
        gstruct, gatom, values, sid, out);

    gather_kernel<<<GATHER_BLOCKS, 256>>>(grad4, out_grad);
}